// round 5
// baseline (speedup 1.0000x reference)
#include <cuda_runtime.h>
#include <cuda_bf16.h>
#include <cuda_fp16.h>
#include <cstdint>
#include <math.h>

#define BB 2
#define SS 2048
#define DIMV 1024
#define NH 16
#define FFV 4096
#define MTOT (BB*SS)          /* 4096 rows */
#define KP1 (3*DIMV)          /* 3072: split-K' for K=1024 */
#define KP2 (3*FFV)           /* 12288: split-K' for K=4096 */

// ---------------- scratch (device globals: allocation-free) ----------------
__device__ float g_qkv[MTOT * 3 * DIMV];
__device__ float g_tmp[MTOT * DIMV];
__device__ float g_x1 [MTOT * DIMV];

__device__ __align__(16) __half g_qs[(size_t)BB * NH * SS * 64];
__device__ __align__(16) __half g_ks[(size_t)BB * NH * SS * 64];
__device__ __align__(16) __half g_vt[(size_t)BB * NH * 64 * SS];

__device__ __align__(16) __nv_bfloat16 g_xb  [MTOT * KP1];
__device__ __align__(16) __nv_bfloat16 g_ctxb[MTOT * KP1];
__device__ __align__(16) __nv_bfloat16 g_x1b [MTOT * KP1];
__device__ __align__(16) __nv_bfloat16 g_hb  [(size_t)MTOT * KP2];
__device__ __align__(16) __nv_bfloat16 g_wqkv[3 * DIMV * KP1];
__device__ __align__(16) __nv_bfloat16 g_wao [DIMV * KP1];
__device__ __align__(16) __nv_bfloat16 g_wgl [(size_t)2 * FFV * KP1];  // interleaved gate/lin
__device__ __align__(16) __nv_bfloat16 g_wfo [DIMV * KP2];

// ---------------- PTX helpers ----------------------------------------------
__device__ __forceinline__ uint32_t smem_u32(const void* p) {
    uint32_t a;
    asm("{ .reg .u64 t; cvta.to.shared.u64 t, %1; cvt.u32.u64 %0, t; }"
        : "=r"(a) : "l"(p));
    return a;
}
__device__ __forceinline__ void cpa16(uint32_t dst, const void* src) {
    asm volatile("cp.async.cg.shared.global [%0], [%1], 16;" :: "r"(dst), "l"(src));
}
#define CP_COMMIT() asm volatile("cp.async.commit_group;" ::: "memory")

#define LDSM4(r, addr) \
    asm volatile("ldmatrix.sync.aligned.m8n8.x4.shared.b16 {%0,%1,%2,%3}, [%4];" \
        : "=r"((r)[0]), "=r"((r)[1]), "=r"((r)[2]), "=r"((r)[3]) : "r"(addr))

#define MMA16816(d, a, b0, b1) \
    asm volatile("mma.sync.aligned.m16n8k16.row.col.f32.bf16.bf16.f32 " \
        "{%0,%1,%2,%3},{%4,%5,%6,%7},{%8,%9},{%0,%1,%2,%3};" \
        : "+f"((d)[0]), "+f"((d)[1]), "+f"((d)[2]), "+f"((d)[3]) \
        : "r"((a)[0]), "r"((a)[1]), "r"((a)[2]), "r"((a)[3]), "r"(b0), "r"(b1))

#define MMAF16(d, a, b0, b1) \
    asm volatile("mma.sync.aligned.m16n8k16.row.col.f32.f16.f16.f32 " \
        "{%0,%1,%2,%3},{%4,%5,%6,%7},{%8,%9},{%0,%1,%2,%3};" \
        : "+f"((d)[0]), "+f"((d)[1]), "+f"((d)[2]), "+f"((d)[3]) \
        : "r"((a)[0]), "r"((a)[1]), "r"((a)[2]), "r"((a)[3]), "r"(b0), "r"(b1))

__device__ __forceinline__ uint32_t pkf16(float lo, float hi) {
    uint32_t r;
    asm("cvt.rn.f16x2.f32 %0, %1, %2;" : "=r"(r) : "f"(hi), "f"(lo));
    return r;
}

// ---------------- bf16 HMMA GEMM: C[M,N] = A[M,Kp] @ W[N,Kp]^T --------------
// CTA 128x128, 8 warps (2x4), warp 64x32, BK=64, 4-stage cp.async pipeline.
// EPI=0: plain fp32 store.  EPI=1: GLU epilogue (interleaved gate/lin cols)
//        h = (lin+lb)*sigmoid(gate+gb) -> split-bf16 HB [hi|hi|lo] over KP2.
#define GSTAGES 4
#define GSTAGE_BYTES 32768          /* A 16KB + B 16KB */
#define GEMM_SMEM (GSTAGES * GSTAGE_BYTES)

template<int EPI>
__global__ void __launch_bounds__(256) gemm_mma_t(
    const __nv_bfloat16* __restrict__ A, const __nv_bfloat16* __restrict__ W,
    float* __restrict__ C, __nv_bfloat16* __restrict__ HB,
    const float* __restrict__ gb, const float* __restrict__ lb,
    int N, int Kp)
{
    extern __shared__ char sm[];
    const uint32_t smb = smem_u32(sm);
    const int tid  = threadIdx.x;
    const int wid  = tid >> 5, lane = tid & 31;
    const int wm   = (wid >> 2) << 6;
    const int wn   = (wid & 3) << 5;
    const int m0   = blockIdx.y << 7, n0 = blockIdx.x << 7;
    const int quad = lane >> 3, l8 = lane & 7;

    float acc[4][4][4];
#pragma unroll
    for (int i = 0; i < 4; ++i)
#pragma unroll
        for (int j = 0; j < 4; ++j)
#pragma unroll
            for (int v = 0; v < 4; ++v) acc[i][j][v] = 0.f;

    auto load_stage = [&](int kt) {
        const int s = kt % GSTAGES;
        const uint32_t sa = smb + s * GSTAGE_BYTES;
        const uint32_t sb = sa + 16384;
        const size_t kbase = (size_t)kt << 6;
#pragma unroll
        for (int p = 0; p < 4; ++p) {
            int chunk = (p << 8) + tid;
            int r = chunk >> 3, kc = chunk & 7;
            cpa16(sa + r * 128 + ((kc ^ (r & 7)) << 4),
                  (const char*)(A + (size_t)(m0 + r) * Kp + kbase + kc * 8));
        }
#pragma unroll
        for (int p = 0; p < 4; ++p) {
            int chunk = (p << 8) + tid;
            int r = chunk >> 3, kc = chunk & 7;
            cpa16(sb + r * 128 + ((kc ^ (r & 7)) << 4),
                  (const char*)(W + (size_t)(n0 + r) * Kp + kbase + kc * 8));
        }
        CP_COMMIT();
    };

    const int nk = Kp >> 6;
    load_stage(0);
    load_stage(1);
    load_stage(2);

    for (int kt = 0; kt < nk; ++kt) {
        const int s = kt % GSTAGES;
        asm volatile("cp.async.wait_group 2;" ::: "memory");
        __syncthreads();
        if (kt + 3 < nk) load_stage(kt + 3); else CP_COMMIT();

        const uint32_t sa = smb + s * GSTAGE_BYTES;
        const uint32_t sb = sa + 16384;
#pragma unroll
        for (int ks = 0; ks < 4; ++ks) {
            const int k0c = ks << 1;
            uint32_t a[4][4], b[2][4];
#pragma unroll
            for (int mf = 0; mf < 4; ++mf) {
                int r  = wm + (mf << 4) + ((quad & 1) << 3) + l8;
                int kc = k0c + (quad >> 1);
                LDSM4(a[mf], sa + r * 128 + ((kc ^ (r & 7)) << 4));
            }
#pragma unroll
            for (int np = 0; np < 2; ++np) {
                int r  = wn + (np << 4) + ((quad >> 1) << 3) + l8;
                int kc = k0c + (quad & 1);
                LDSM4(b[np], sb + r * 128 + ((kc ^ (r & 7)) << 4));
            }
#pragma unroll
            for (int mf = 0; mf < 4; ++mf) {
#pragma unroll
                for (int np = 0; np < 2; ++np) {
                    MMA16816(acc[mf][2 * np],     a[mf], b[np][0], b[np][1]);
                    MMA16816(acc[mf][2 * np + 1], a[mf], b[np][2], b[np][3]);
                }
            }
        }
    }

    const int tr = lane >> 2, tc = (lane & 3) << 1;
    if (EPI == 0) {
#pragma unroll
        for (int mf = 0; mf < 4; ++mf) {
            int row = m0 + wm + (mf << 4) + tr;
            float* c0 = C + (size_t)row * N + n0 + wn;
            float* c1 = c0 + (size_t)8 * N;
#pragma unroll
            for (int nf = 0; nf < 4; ++nf) {
                *(float2*)(c0 + (nf << 3) + tc) = make_float2(acc[mf][nf][0], acc[mf][nf][1]);
                *(float2*)(c1 + (nf << 3) + tc) = make_float2(acc[mf][nf][2], acc[mf][nf][3]);
            }
        }
    } else {
        // interleaved cols: even col = gate_c, odd col = lin_c, c = gcol>>1
#pragma unroll
        for (int mf = 0; mf < 4; ++mf) {
            int row0 = m0 + wm + (mf << 4) + tr;
#pragma unroll
            for (int nf = 0; nf < 4; ++nf) {
                int c = (n0 + wn + (nf << 3) + tc) >> 1;
                float gbv = gb[c], lbv = lb[c];
                float h0 = (acc[mf][nf][1] + lbv) *
                           (1.f / (1.f + __expf(-(acc[mf][nf][0] + gbv))));
                float h1 = (acc[mf][nf][3] + lbv) *
                           (1.f / (1.f + __expf(-(acc[mf][nf][2] + gbv))));
                __nv_bfloat16 hh0 = __float2bfloat16(h0);
                __nv_bfloat16 hh1 = __float2bfloat16(h1);
                __nv_bfloat16 hl0 = __float2bfloat16(h0 - __bfloat162float(hh0));
                __nv_bfloat16 hl1 = __float2bfloat16(h1 - __bfloat162float(hh1));
                __nv_bfloat16* p0 = HB + (size_t)row0 * KP2 + c;
                __nv_bfloat16* p1 = p0 + (size_t)8 * KP2;
                p0[0] = hh0; p0[FFV] = hh0; p0[2 * FFV] = hl0;
                p1[0] = hh1; p1[FFV] = hh1; p1[2 * FFV] = hl1;
            }
        }
    }
}

// ---------------- fp32 -> split bf16 conversions ----------------------------
__global__ void convert_act(const float* __restrict__ X, __nv_bfloat16* __restrict__ Y,
                            int total, int K)
{
    int idx = blockIdx.x * blockDim.x + threadIdx.x;
    if (idx >= total) return;
    int row = idx / K, col = idx - row * K;
    float x = X[idx];
    __nv_bfloat16 hi = __float2bfloat16(x);
    __nv_bfloat16 lo = __float2bfloat16(x - __bfloat162float(hi));
    size_t b = (size_t)row * (3 * K) + col;
    Y[b] = hi; Y[b + K] = hi; Y[b + 2 * K] = lo;
}
__global__ void convert_w(const float* __restrict__ X, __nv_bfloat16* __restrict__ Y,
                          int total, int K)
{
    int idx = blockIdx.x * blockDim.x + threadIdx.x;
    if (idx >= total) return;
    int row = idx / K, col = idx - row * K;
    float x = X[idx];
    __nv_bfloat16 hi = __float2bfloat16(x);
    __nv_bfloat16 lo = __float2bfloat16(x - __bfloat162float(hi));
    size_t b = (size_t)row * (3 * K) + col;
    Y[b] = hi; Y[b + K] = lo; Y[b + 2 * K] = hi;
}
// gate row c -> interleaved row 2c ; lin row c -> row 2c+1  (split [hi|lo|hi])
__global__ void convert_w_glu(const float* __restrict__ G, const float* __restrict__ L,
                              __nv_bfloat16* __restrict__ Y)
{
    int idx = blockIdx.x * blockDim.x + threadIdx.x;
    if (idx >= FFV * DIMV) return;
    int row = idx >> 10, col = idx & (DIMV - 1);
    float gv = G[idx], lv = L[idx];
    __nv_bfloat16 gh = __float2bfloat16(gv);
    __nv_bfloat16 gl = __float2bfloat16(gv - __bfloat162float(gh));
    __nv_bfloat16 lh = __float2bfloat16(lv);
    __nv_bfloat16 ll = __float2bfloat16(lv - __bfloat162float(lh));
    size_t bg = (size_t)(2 * row) * KP1 + col;
    size_t bl = bg + KP1;
    Y[bg] = gh; Y[bg + DIMV] = gl; Y[bg + 2 * DIMV] = gh;
    Y[bl] = lh; Y[bl + DIMV] = ll; Y[bl + 2 * DIMV] = lh;
}

// ---------------- q,k prep: RoPE + scale + f16, head-major layout -----------
__global__ void qkprep(const float* __restrict__ qkv,
                       __half* __restrict__ qs, __half* __restrict__ ks)
{
    int idx = blockIdx.x * blockDim.x + threadIdx.x;
    if (idx >= BB * SS * NH * 32) return;
    int i = idx & 31;
    int h = (idx >> 5) & 15;
    int s = (idx >> 9) & (SS - 1);
    int b = idx >> 20;
    float inv_freq = expf(-(float)i * (9.210340371976184f / 32.0f));
    float ph = (float)s * inv_freq;
    float co = cosf(ph), si = sinf(ph);
    size_t base = ((size_t)(b * SS + s) * 3) * DIMV + h * 64;
    size_t ob = ((size_t)(b * NH + h) * SS + s) * 64;
    float x1 = qkv[base + i], x2 = qkv[base + 32 + i];
    qs[ob + i]      = __float2half((x1 * co - x2 * si) * 0.125f);
    qs[ob + 32 + i] = __float2half((x1 * si + x2 * co) * 0.125f);
    base += DIMV;
    x1 = qkv[base + i]; x2 = qkv[base + 32 + i];
    ks[ob + i]      = __float2half(x1 * co - x2 * si);
    ks[ob + 32 + i] = __float2half(x1 * si + x2 * co);
}

// ---------------- v prep: transpose to [b,h,d,S] f16 ------------------------
__global__ __launch_bounds__(256) void vprep(const float* __restrict__ qkv,
                                             __half* __restrict__ vtb)
{
    __shared__ float t[64][65];
    int s0 = blockIdx.x << 6, h = blockIdx.y, b = blockIdx.z;
    int tid = threadIdx.x;
#pragma unroll
    for (int p = 0; p < 16; ++p) {
        int r = (p << 2) + (tid >> 6), d = tid & 63;
        t[r][d] = qkv[((size_t)(b * SS + s0 + r) * 3 + 2) * DIMV + h * 64 + d];
    }
    __syncthreads();
    size_t ob = ((size_t)(b * NH + h) * 64) * SS;
#pragma unroll
    for (int p = 0; p < 16; ++p) {
        int d = (p << 2) + (tid >> 6), sl = tid & 63;
        vtb[ob + (size_t)d * SS + s0 + sl] = __float2half(t[sl][d]);
    }
}

// ---------------- flash attention, f16 HMMA ---------------------------------
__global__ void __launch_bounds__(128) attn_mma(
    const __half* __restrict__ qs, const __half* __restrict__ ks,
    const __half* __restrict__ vt, __nv_bfloat16* __restrict__ ctxb)
{
    __shared__ __align__(16) char sm[40960];   // Q 8KB | 2 x (K 8KB + V 8KB)
    const uint32_t Qs = smem_u32(sm);
    const uint32_t Ss = Qs + 8192;
    const int qt = gridDim.x - 1 - blockIdx.x;  // heavy tiles first
    const int h = blockIdx.y, b = blockIdx.z;
    const int q0 = qt << 6;
    const int tid = threadIdx.x, wid = tid >> 5, lane = tid & 31;
    const int quad = lane >> 3, l8 = lane & 7;
    const int tr = lane >> 2, tc = (lane & 3) << 1;
    const int wq0 = wid << 4;
    const size_t bh = (size_t)(b * NH + h);
    const __half* qrow = qs + (bh * SS + q0) * 64;
    const __half* krow = ks + bh * SS * 64;
    const __half* vrow = vt + bh * 64 * SS;

    for (int c = tid; c < 512; c += 128) {
        int r = c >> 3, kc = c & 7;
        cpa16(Qs + r * 128 + ((kc ^ (r & 7)) << 4),
              (const char*)(qrow + (size_t)r * 64) + kc * 16);
    }
    CP_COMMIT();

    auto load_stage = [&](int kt) {
        uint32_t Kst = Ss + (kt & 1) * 16384, Vst = Kst + 8192;
        const __half* kr = krow + ((size_t)kt << 6) * 64;
        int k0 = kt << 6;
        for (int c = tid; c < 512; c += 128) {
            int r = c >> 3, kc = c & 7;
            cpa16(Kst + r * 128 + ((kc ^ (r & 7)) << 4),
                  (const char*)(kr + (size_t)r * 64) + kc * 16);
        }
        for (int c = tid; c < 512; c += 128) {
            int r = c >> 3, kc = c & 7;
            cpa16(Vst + r * 128 + ((kc ^ (r & 7)) << 4),
                  (const char*)(vrow + (size_t)r * SS + k0) + kc * 16);
        }
        CP_COMMIT();
    };

    float m0r = -1e30f, m1r = -1e30f, l0 = 0.f, l1 = 0.f;
    float oacc[8][4];
#pragma unroll
    for (int i = 0; i < 8; ++i)
#pragma unroll
        for (int j = 0; j < 4; ++j) oacc[i][j] = 0.f;

    const int nt = qt + 1;
    load_stage(0);

    for (int kt = 0; kt < nt; ++kt) {
        if (kt + 1 < nt) {
            load_stage(kt + 1);
            asm volatile("cp.async.wait_group 1;" ::: "memory");
        } else {
            asm volatile("cp.async.wait_group 0;" ::: "memory");
        }
        __syncthreads();
        const uint32_t Kst = Ss + (kt & 1) * 16384, Vst = Kst + 8192;

        float sacc[8][4];
#pragma unroll
        for (int i = 0; i < 8; ++i)
#pragma unroll
            for (int j = 0; j < 4; ++j) sacc[i][j] = 0.f;
#pragma unroll
        for (int ksp = 0; ksp < 4; ++ksp) {
            uint32_t a[4];
            {
                int r = wq0 + ((quad & 1) << 3) + l8;
                int kc = 2 * ksp + (quad >> 1);
                LDSM4(a, Qs + r * 128 + ((kc ^ (r & 7)) << 4));
            }
#pragma unroll
            for (int np = 0; np < 4; ++np) {
                uint32_t bf[4];
                int r = (np << 4) + ((quad >> 1) << 3) + l8;
                int kc = 2 * ksp + (quad & 1);
                LDSM4(bf, Kst + r * 128 + ((kc ^ (r & 7)) << 4));
                MMAF16(sacc[2 * np],     a, bf[0], bf[1]);
                MMAF16(sacc[2 * np + 1], a, bf[2], bf[3]);
            }
        }

        if (kt == qt) {
            int r0 = wq0 + tr, r1 = r0 + 8;
#pragma unroll
            for (int nf = 0; nf < 8; ++nf) {
                int c0 = (nf << 3) + tc;
                if (c0     > r0) sacc[nf][0] = -1e30f;
                if (c0 + 1 > r0) sacc[nf][1] = -1e30f;
                if (c0     > r1) sacc[nf][2] = -1e30f;
                if (c0 + 1 > r1) sacc[nf][3] = -1e30f;
            }
        }

        float mx0 = -1e30f, mx1 = -1e30f;
#pragma unroll
        for (int nf = 0; nf < 8; ++nf) {
            mx0 = fmaxf(mx0, fmaxf(sacc[nf][0], sacc[nf][1]));
            mx1 = fmaxf(mx1, fmaxf(sacc[nf][2], sacc[nf][3]));
        }
        mx0 = fmaxf(mx0, __shfl_xor_sync(0xffffffffu, mx0, 1));
        mx0 = fmaxf(mx0, __shfl_xor_sync(0xffffffffu, mx0, 2));
        mx1 = fmaxf(mx1, __shfl_xor_sync(0xffffffffu, mx1, 1));
        mx1 = fmaxf(mx1, __shfl_xor_sync(0xffffffffu, mx1, 2));
        float mn0 = fmaxf(m0r, mx0), mn1 = fmaxf(m1r, mx1);
        float al0 = __expf(m0r - mn0), al1 = __expf(m1r - mn1);
        float rs0 = 0.f, rs1 = 0.f;
#pragma unroll
        for (int nf = 0; nf < 8; ++nf) {
            sacc[nf][0] = __expf(sacc[nf][0] - mn0);
            sacc[nf][1] = __expf(sacc[nf][1] - mn0);
            sacc[nf][2] = __expf(sacc[nf][2] - mn1);
            sacc[nf][3] = __expf(sacc[nf][3] - mn1);
            rs0 += sacc[nf][0] + sacc[nf][1];
            rs1 += sacc[nf][2] + sacc[nf][3];
        }
        rs0 += __shfl_xor_sync(0xffffffffu, rs0, 1);
        rs0 += __shfl_xor_sync(0xffffffffu, rs0, 2);
        rs1 += __shfl_xor_sync(0xffffffffu, rs1, 1);
        rs1 += __shfl_xor_sync(0xffffffffu, rs1, 2);
        l0 = l0 * al0 + rs0;
        l1 = l1 * al1 + rs1;
        m0r = mn0; m1r = mn1;
#pragma unroll
        for (int nf = 0; nf < 8; ++nf) {
            oacc[nf][0] *= al0; oacc[nf][1] *= al0;
            oacc[nf][2] *= al1; oacc[nf][3] *= al1;
        }

#pragma unroll
        for (int ksp = 0; ksp < 4; ++ksp) {
            uint32_t pa[4];
            pa[0] = pkf16(sacc[2 * ksp][0],     sacc[2 * ksp][1]);
            pa[1] = pkf16(sacc[2 * ksp][2],     sacc[2 * ksp][3]);
            pa[2] = pkf16(sacc[2 * ksp + 1][0], sacc[2 * ksp + 1][1]);
            pa[3] = pkf16(sacc[2 * ksp + 1][2], sacc[2 * ksp + 1][3]);
#pragma unroll
            for (int np = 0; np < 4; ++np) {
                uint32_t bf[4];
                int r = (np << 4) + ((quad >> 1) << 3) + l8;
                int kc = 2 * ksp + (quad & 1);
                LDSM4(bf, Vst + r * 128 + ((kc ^ (r & 7)) << 4));
                MMAF16(oacc[2 * np],     pa, bf[0], bf[1]);
                MMAF16(oacc[2 * np + 1], pa, bf[2], bf[3]);
            }
        }
        __syncthreads();
    }

    float i0 = 1.f / l0, i1 = 1.f / l1;
    int row0 = q0 + wq0 + tr;
    __nv_bfloat16* p0 = ctxb + ((size_t)b * SS + row0) * KP1 + h * 64;
    __nv_bfloat16* p1 = p0 + (size_t)8 * KP1;
#pragma unroll
    for (int nf = 0; nf < 8; ++nf) {
        int co = (nf << 3) + tc;
        float v0 = oacc[nf][0] * i0, v1 = oacc[nf][1] * i0;
        float v2 = oacc[nf][2] * i1, v3 = oacc[nf][3] * i1;
        __nv_bfloat16 h0 = __float2bfloat16(v0), h1 = __float2bfloat16(v1);
        __nv_bfloat16 h2 = __float2bfloat16(v2), h3 = __float2bfloat16(v3);
        __nv_bfloat162 hp0 = {h0, h1}, hp1 = {h2, h3};
        __nv_bfloat162 lp0 = {__float2bfloat16(v0 - __bfloat162float(h0)),
                              __float2bfloat16(v1 - __bfloat162float(h1))};
        __nv_bfloat162 lp1 = {__float2bfloat16(v2 - __bfloat162float(h2)),
                              __float2bfloat16(v3 - __bfloat162float(h3))};
        *(__nv_bfloat162*)(p0 + co)            = hp0;
        *(__nv_bfloat162*)(p0 + co + DIMV)     = hp0;
        *(__nv_bfloat162*)(p0 + co + 2 * DIMV) = lp0;
        *(__nv_bfloat162*)(p1 + co)            = hp1;
        *(__nv_bfloat162*)(p1 + co + DIMV)     = hp1;
        *(__nv_bfloat162*)(p1 + co + 2 * DIMV) = lp1;
    }
}

// ---------------- out = rms_norm(a + b) * scale  (+ optional bf16 split) ----
__global__ __launch_bounds__(256) void addnorm_kernel(
    const float* __restrict__ a, const float* __restrict__ bbuf,
    const float* __restrict__ scale, float* __restrict__ out,
    __nv_bfloat16* __restrict__ outb)
{
    const int row = blockIdx.x;
    const int tid = threadIdx.x;
    const size_t base = (size_t)row * DIMV;
    float v[4];
    float ss = 0.f;
#pragma unroll
    for (int j = 0; j < 4; ++j) {
        int c = tid + j * 256;
        v[j] = a[base + c] + bbuf[base + c];
        ss = fmaf(v[j], v[j], ss);
    }
    __shared__ float red[8];
#pragma unroll
    for (int o = 16; o; o >>= 1) ss += __shfl_xor_sync(0xffffffffu, ss, o);
    if ((tid & 31) == 0) red[tid >> 5] = ss;
    __syncthreads();
    if (tid < 8) {
        float t = red[tid];
#pragma unroll
        for (int o = 4; o; o >>= 1) t += __shfl_xor_sync(0xffu, t, o);
        if (tid == 0) red[0] = t;
    }
    __syncthreads();
    float rms = sqrtf(red[0] * (1.f / 1024.f));
    float inv = 1.f / (rms + 1e-8f);
#pragma unroll
    for (int j = 0; j < 4; ++j) {
        int c = tid + j * 256;
        float o = scale[c] * v[j] * inv;
        out[base + c] = o;
        if (outb) {
            __nv_bfloat16 hi = __float2bfloat16(o);
            __nv_bfloat16 lo = __float2bfloat16(o - __bfloat162float(hi));
            size_t bb2 = (size_t)row * KP1 + c;
            outb[bb2] = hi; outb[bb2 + DIMV] = hi; outb[bb2 + 2 * DIMV] = lo;
        }
    }
}

// ---------------- launcher --------------------------------------------------
extern "C" void kernel_launch(void* const* d_in, const int* in_sizes, int n_in,
                              void* d_out, int out_size)
{
    (void)in_sizes; (void)n_in; (void)out_size;
    const float* x          = (const float*)d_in[0];
    const float* qkv_w      = (const float*)d_in[2];
    const float* attn_out_w = (const float*)d_in[3];
    const float* gate_w     = (const float*)d_in[4];
    const float* gate_b     = (const float*)d_in[5];
    const float* lin_w      = (const float*)d_in[6];
    const float* lin_b      = (const float*)d_in[7];
    const float* ff_out_w   = (const float*)d_in[8];
    const float* n1         = (const float*)d_in[9];
    const float* n2         = (const float*)d_in[10];
    float* out = (float*)d_out;

    float *qkv, *tmp, *x1;
    __half *qsb, *ksb, *vtb;
    __nv_bfloat16 *xb, *ctxb, *x1b, *hb, *wqkv, *wao, *wgl, *wfo;
    cudaGetSymbolAddress((void**)&qkv,  g_qkv);
    cudaGetSymbolAddress((void**)&tmp,  g_tmp);
    cudaGetSymbolAddress((void**)&x1,   g_x1);
    cudaGetSymbolAddress((void**)&qsb,  g_qs);
    cudaGetSymbolAddress((void**)&ksb,  g_ks);
    cudaGetSymbolAddress((void**)&vtb,  g_vt);
    cudaGetSymbolAddress((void**)&xb,   g_xb);
    cudaGetSymbolAddress((void**)&ctxb, g_ctxb);
    cudaGetSymbolAddress((void**)&x1b,  g_x1b);
    cudaGetSymbolAddress((void**)&hb,   g_hb);
    cudaGetSymbolAddress((void**)&wqkv, g_wqkv);
    cudaGetSymbolAddress((void**)&wao,  g_wao);
    cudaGetSymbolAddress((void**)&wgl,  g_wgl);
    cudaGetSymbolAddress((void**)&wfo,  g_wfo);

    cudaFuncSetAttribute(gemm_mma_t<0>, cudaFuncAttributeMaxDynamicSharedMemorySize, GEMM_SMEM);
    cudaFuncSetAttribute(gemm_mma_t<1>, cudaFuncAttributeMaxDynamicSharedMemorySize, GEMM_SMEM);

    // weight + input conversions (fp32 -> split bf16)
    convert_w    <<<(3*DIMV*DIMV + 255)/256, 256>>>(qkv_w,      wqkv, 3*DIMV*DIMV, DIMV);
    convert_w    <<<(DIMV*DIMV   + 255)/256, 256>>>(attn_out_w, wao,  DIMV*DIMV,   DIMV);
    convert_w_glu<<<(FFV*DIMV    + 255)/256, 256>>>(gate_w, lin_w, wgl);
    convert_w    <<<(DIMV*FFV    + 255)/256, 256>>>(ff_out_w,   wfo,  DIMV*FFV,    FFV);
    convert_act  <<<(MTOT*DIMV   + 255)/256, 256>>>(x,          xb,   MTOT*DIMV,   DIMV);

    // 1. QKV projection
    gemm_mma_t<0><<<dim3(3*DIMV/128, MTOT/128), 256, GEMM_SMEM>>>(
        xb, wqkv, qkv, nullptr, nullptr, nullptr, 3*DIMV, KP1);
    // 2. q/k prep (RoPE + scale -> f16) and v transpose
    qkprep<<<(BB*SS*NH*32 + 255)/256, 256>>>(qkv, qsb, ksb);
    vprep <<<dim3(SS/64, NH, BB), 256>>>(qkv, vtb);
    // 3. flash attention (f16 HMMA) -> split-bf16 ctx
    attn_mma<<<dim3(SS/64, NH, BB), 128>>>(qsb, ksb, vtb, ctxb);
    // 4. output projection
    gemm_mma_t<0><<<dim3(DIMV/128, MTOT/128), 256, GEMM_SMEM>>>(
        ctxb, wao, tmp, nullptr, nullptr, nullptr, DIMV, KP1);
    // 5. x1 = rmsnorm(x + proj), also emit split bf16
    addnorm_kernel<<<MTOT, 256>>>(x, tmp, n1, x1, x1b);
    // 6-8. fused gate+lin GEMM with GLU epilogue -> split-bf16 hb
    gemm_mma_t<1><<<dim3(2*FFV/128, MTOT/128), 256, GEMM_SMEM>>>(
        x1b, wgl, nullptr, hb, gate_b, lin_b, 2*FFV, KP1);
    // 9. ff out
    gemm_mma_t<0><<<dim3(DIMV/128, MTOT/128), 256, GEMM_SMEM>>>(
        hb, wfo, tmp, nullptr, nullptr, nullptr, DIMV, KP2);
    // 10. out = rmsnorm(x1 + ff)
    addnorm_kernel<<<MTOT, 256>>>(x1, tmp, n2, out, nullptr);
}

// round 6
// speedup vs baseline: 1.1239x; 1.1239x over previous
#include <cuda_runtime.h>
#include <cuda_bf16.h>
#include <cuda_fp16.h>
#include <cstdint>
#include <math.h>

#define BB 2
#define SS 2048
#define DIMV 1024
#define NH 16
#define FFV 4096
#define MTOT (BB*SS)          /* 4096 rows */
#define KP1 (3*DIMV)          /* 3072: split-K' for K=1024 */
#define KP2 (3*FFV)           /* 12288: split-K' for K=4096 */

// ---------------- scratch (device globals: allocation-free) ----------------
__device__ float g_qkv[MTOT * 3 * DIMV];
__device__ float g_tmp[MTOT * DIMV];
__device__ float g_x1 [MTOT * DIMV];

__device__ __align__(16) __half g_qs[(size_t)BB * NH * SS * 64];
__device__ __align__(16) __half g_ks[(size_t)BB * NH * SS * 64];
__device__ __align__(16) __half g_vt[(size_t)BB * NH * 64 * SS];

__device__ __align__(16) __nv_bfloat16 g_xb  [MTOT * KP1];
__device__ __align__(16) __nv_bfloat16 g_ctxb[MTOT * KP1];
__device__ __align__(16) __nv_bfloat16 g_x1b [MTOT * KP1];
__device__ __align__(16) __nv_bfloat16 g_hb  [(size_t)MTOT * KP2];
__device__ __align__(16) __nv_bfloat16 g_wqkv[3 * DIMV * KP1];
__device__ __align__(16) __nv_bfloat16 g_wao [DIMV * KP1];
__device__ __align__(16) __nv_bfloat16 g_wgl [(size_t)2 * FFV * KP1];  // interleaved gate/lin
__device__ __align__(16) __nv_bfloat16 g_wfo [DIMV * KP2];

// ---------------- PTX helpers ----------------------------------------------
__device__ __forceinline__ uint32_t smem_u32(const void* p) {
    uint32_t a;
    asm("{ .reg .u64 t; cvta.to.shared.u64 t, %1; cvt.u32.u64 %0, t; }"
        : "=r"(a) : "l"(p));
    return a;
}
__device__ __forceinline__ void cpa16(uint32_t dst, const void* src) {
    asm volatile("cp.async.cg.shared.global [%0], [%1], 16;" :: "r"(dst), "l"(src));
}
#define CP_COMMIT() asm volatile("cp.async.commit_group;" ::: "memory")

#define LDSM4(r, addr) \
    asm volatile("ldmatrix.sync.aligned.m8n8.x4.shared.b16 {%0,%1,%2,%3}, [%4];" \
        : "=r"((r)[0]), "=r"((r)[1]), "=r"((r)[2]), "=r"((r)[3]) : "r"(addr))

#define MMA16816(d, a, b0, b1) \
    asm volatile("mma.sync.aligned.m16n8k16.row.col.f32.bf16.bf16.f32 " \
        "{%0,%1,%2,%3},{%4,%5,%6,%7},{%8,%9},{%0,%1,%2,%3};" \
        : "+f"((d)[0]), "+f"((d)[1]), "+f"((d)[2]), "+f"((d)[3]) \
        : "r"((a)[0]), "r"((a)[1]), "r"((a)[2]), "r"((a)[3]), "r"(b0), "r"(b1))

#define MMAF16(d, a, b0, b1) \
    asm volatile("mma.sync.aligned.m16n8k16.row.col.f32.f16.f16.f32 " \
        "{%0,%1,%2,%3},{%4,%5,%6,%7},{%8,%9},{%0,%1,%2,%3};" \
        : "+f"((d)[0]), "+f"((d)[1]), "+f"((d)[2]), "+f"((d)[3]) \
        : "r"((a)[0]), "r"((a)[1]), "r"((a)[2]), "r"((a)[3]), "r"(b0), "r"(b1))

__device__ __forceinline__ uint32_t pkf16(float lo, float hi) {
    uint32_t r;
    asm("cvt.rn.f16x2.f32 %0, %1, %2;" : "=r"(r) : "f"(hi), "f"(lo));
    return r;
}

// ---------------- bf16 HMMA GEMM: C[M,N] = A[M,Kp] @ W[N,Kp]^T --------------
// CTA 128x128, 8 warps (2x4), warp 64x32, BK=64, 3-stage cp.async pipeline
// (96KB smem -> 2 CTAs/SM).
// EPI=0: plain fp32 store.  EPI=1: GLU epilogue (interleaved gate/lin cols)
//        h = (lin+lb)*sigmoid(gate+gb) -> split-bf16 HB [hi|hi|lo] over KP2.
#define GSTAGES 3
#define GSTAGE_BYTES 32768          /* A 16KB + B 16KB */
#define GEMM_SMEM (GSTAGES * GSTAGE_BYTES)

template<int EPI>
__global__ void __launch_bounds__(256) gemm_mma_t(
    const __nv_bfloat16* __restrict__ A, const __nv_bfloat16* __restrict__ W,
    float* __restrict__ C, __nv_bfloat16* __restrict__ HB,
    const float* __restrict__ gb, const float* __restrict__ lb,
    int N, int Kp)
{
    extern __shared__ char sm[];
    const uint32_t smb = smem_u32(sm);
    const int tid  = threadIdx.x;
    const int wid  = tid >> 5, lane = tid & 31;
    const int wm   = (wid >> 2) << 6;
    const int wn   = (wid & 3) << 5;
    const int m0   = blockIdx.y << 7, n0 = blockIdx.x << 7;
    const int quad = lane >> 3, l8 = lane & 7;

    float acc[4][4][4];
#pragma unroll
    for (int i = 0; i < 4; ++i)
#pragma unroll
        for (int j = 0; j < 4; ++j)
#pragma unroll
            for (int v = 0; v < 4; ++v) acc[i][j][v] = 0.f;

    auto load_stage = [&](int kt) {
        const int s = kt % GSTAGES;
        const uint32_t sa = smb + s * GSTAGE_BYTES;
        const uint32_t sb = sa + 16384;
        const size_t kbase = (size_t)kt << 6;
#pragma unroll
        for (int p = 0; p < 4; ++p) {
            int chunk = (p << 8) + tid;
            int r = chunk >> 3, kc = chunk & 7;
            cpa16(sa + r * 128 + ((kc ^ (r & 7)) << 4),
                  (const char*)(A + (size_t)(m0 + r) * Kp + kbase + kc * 8));
        }
#pragma unroll
        for (int p = 0; p < 4; ++p) {
            int chunk = (p << 8) + tid;
            int r = chunk >> 3, kc = chunk & 7;
            cpa16(sb + r * 128 + ((kc ^ (r & 7)) << 4),
                  (const char*)(W + (size_t)(n0 + r) * Kp + kbase + kc * 8));
        }
        CP_COMMIT();
    };

    const int nk = Kp >> 6;
    load_stage(0);
    load_stage(1);

    for (int kt = 0; kt < nk; ++kt) {
        const int s = kt % GSTAGES;
        asm volatile("cp.async.wait_group 1;" ::: "memory");
        __syncthreads();
        if (kt + 2 < nk) load_stage(kt + 2); else CP_COMMIT();

        const uint32_t sa = smb + s * GSTAGE_BYTES;
        const uint32_t sb = sa + 16384;
#pragma unroll
        for (int ks = 0; ks < 4; ++ks) {
            const int k0c = ks << 1;
            uint32_t a[4][4], b[2][4];
#pragma unroll
            for (int mf = 0; mf < 4; ++mf) {
                int r  = wm + (mf << 4) + ((quad & 1) << 3) + l8;
                int kc = k0c + (quad >> 1);
                LDSM4(a[mf], sa + r * 128 + ((kc ^ (r & 7)) << 4));
            }
#pragma unroll
            for (int np = 0; np < 2; ++np) {
                int r  = wn + (np << 4) + ((quad >> 1) << 3) + l8;
                int kc = k0c + (quad & 1);
                LDSM4(b[np], sb + r * 128 + ((kc ^ (r & 7)) << 4));
            }
#pragma unroll
            for (int mf = 0; mf < 4; ++mf) {
#pragma unroll
                for (int np = 0; np < 2; ++np) {
                    MMA16816(acc[mf][2 * np],     a[mf], b[np][0], b[np][1]);
                    MMA16816(acc[mf][2 * np + 1], a[mf], b[np][2], b[np][3]);
                }
            }
        }
    }

    const int tr = lane >> 2, tc = (lane & 3) << 1;
    if (EPI == 0) {
#pragma unroll
        for (int mf = 0; mf < 4; ++mf) {
            int row = m0 + wm + (mf << 4) + tr;
            float* c0 = C + (size_t)row * N + n0 + wn;
            float* c1 = c0 + (size_t)8 * N;
#pragma unroll
            for (int nf = 0; nf < 4; ++nf) {
                *(float2*)(c0 + (nf << 3) + tc) = make_float2(acc[mf][nf][0], acc[mf][nf][1]);
                *(float2*)(c1 + (nf << 3) + tc) = make_float2(acc[mf][nf][2], acc[mf][nf][3]);
            }
        }
    } else {
        // interleaved cols: even col = gate_c, odd col = lin_c, c = gcol>>1.
        // lane pairs (lane, lane^1) hold consecutive c -> even lanes store bf16x2.
#pragma unroll
        for (int mf = 0; mf < 4; ++mf) {
            int row0 = m0 + wm + (mf << 4) + tr;
#pragma unroll
            for (int nf = 0; nf < 4; ++nf) {
                int c = (n0 + wn + (nf << 3) + tc) >> 1;
                float gbv = gb[c], lbv = lb[c];
                float h0 = (acc[mf][nf][1] + lbv) *
                           (1.f / (1.f + __expf(-(acc[mf][nf][0] + gbv))));
                float h1 = (acc[mf][nf][3] + lbv) *
                           (1.f / (1.f + __expf(-(acc[mf][nf][2] + gbv))));
                float h0p = __shfl_xor_sync(0xffffffffu, h0, 1);
                float h1p = __shfl_xor_sync(0xffffffffu, h1, 1);
                if ((lane & 1) == 0) {
                    __nv_bfloat16 a0 = __float2bfloat16(h0), b0 = __float2bfloat16(h0p);
                    __nv_bfloat16 a1 = __float2bfloat16(h1), b1 = __float2bfloat16(h1p);
                    __nv_bfloat162 hi0 = {a0, b0}, hi1 = {a1, b1};
                    __nv_bfloat162 lo0 = {__float2bfloat16(h0 - __bfloat162float(a0)),
                                          __float2bfloat16(h0p - __bfloat162float(b0))};
                    __nv_bfloat162 lo1 = {__float2bfloat16(h1 - __bfloat162float(a1)),
                                          __float2bfloat16(h1p - __bfloat162float(b1))};
                    __nv_bfloat16* p0 = HB + (size_t)row0 * KP2 + c;
                    __nv_bfloat16* p1 = p0 + (size_t)8 * KP2;
                    *(__nv_bfloat162*)(p0)            = hi0;
                    *(__nv_bfloat162*)(p0 + FFV)      = hi0;
                    *(__nv_bfloat162*)(p0 + 2 * FFV)  = lo0;
                    *(__nv_bfloat162*)(p1)            = hi1;
                    *(__nv_bfloat162*)(p1 + FFV)      = hi1;
                    *(__nv_bfloat162*)(p1 + 2 * FFV)  = lo1;
                }
            }
        }
    }
}

// ---------------- fp32 -> split bf16 conversions ----------------------------
__global__ void convert_act(const float* __restrict__ X, __nv_bfloat16* __restrict__ Y,
                            int total, int K)
{
    int idx = blockIdx.x * blockDim.x + threadIdx.x;
    if (idx >= total) return;
    int row = idx / K, col = idx - row * K;
    float x = X[idx];
    __nv_bfloat16 hi = __float2bfloat16(x);
    __nv_bfloat16 lo = __float2bfloat16(x - __bfloat162float(hi));
    size_t b = (size_t)row * (3 * K) + col;
    Y[b] = hi; Y[b + K] = hi; Y[b + 2 * K] = lo;
}
__global__ void convert_w(const float* __restrict__ X, __nv_bfloat16* __restrict__ Y,
                          int total, int K)
{
    int idx = blockIdx.x * blockDim.x + threadIdx.x;
    if (idx >= total) return;
    int row = idx / K, col = idx - row * K;
    float x = X[idx];
    __nv_bfloat16 hi = __float2bfloat16(x);
    __nv_bfloat16 lo = __float2bfloat16(x - __bfloat162float(hi));
    size_t b = (size_t)row * (3 * K) + col;
    Y[b] = hi; Y[b + K] = lo; Y[b + 2 * K] = hi;
}
// gate row c -> interleaved row 2c ; lin row c -> row 2c+1  (split [hi|lo|hi])
__global__ void convert_w_glu(const float* __restrict__ G, const float* __restrict__ L,
                              __nv_bfloat16* __restrict__ Y)
{
    int idx = blockIdx.x * blockDim.x + threadIdx.x;
    if (idx >= FFV * DIMV) return;
    int row = idx >> 10, col = idx & (DIMV - 1);
    float gv = G[idx], lv = L[idx];
    __nv_bfloat16 gh = __float2bfloat16(gv);
    __nv_bfloat16 gl = __float2bfloat16(gv - __bfloat162float(gh));
    __nv_bfloat16 lh = __float2bfloat16(lv);
    __nv_bfloat16 ll = __float2bfloat16(lv - __bfloat162float(lh));
    size_t bg = (size_t)(2 * row) * KP1 + col;
    size_t bl = bg + KP1;
    Y[bg] = gh; Y[bg + DIMV] = gl; Y[bg + 2 * DIMV] = gh;
    Y[bl] = lh; Y[bl + DIMV] = ll; Y[bl + 2 * DIMV] = lh;
}

// ---------------- q,k prep: RoPE + scale + f16, head-major layout -----------
__global__ void qkprep(const float* __restrict__ qkv,
                       __half* __restrict__ qs, __half* __restrict__ ks)
{
    int idx = blockIdx.x * blockDim.x + threadIdx.x;
    if (idx >= BB * SS * NH * 32) return;
    int i = idx & 31;
    int h = (idx >> 5) & 15;
    int s = (idx >> 9) & (SS - 1);
    int b = idx >> 20;
    float inv_freq = expf(-(float)i * (9.210340371976184f / 32.0f));
    float ph = (float)s * inv_freq;
    float co = cosf(ph), si = sinf(ph);
    size_t base = ((size_t)(b * SS + s) * 3) * DIMV + h * 64;
    size_t ob = ((size_t)(b * NH + h) * SS + s) * 64;
    float x1 = qkv[base + i], x2 = qkv[base + 32 + i];
    qs[ob + i]      = __float2half((x1 * co - x2 * si) * 0.125f);
    qs[ob + 32 + i] = __float2half((x1 * si + x2 * co) * 0.125f);
    base += DIMV;
    x1 = qkv[base + i]; x2 = qkv[base + 32 + i];
    ks[ob + i]      = __float2half(x1 * co - x2 * si);
    ks[ob + 32 + i] = __float2half(x1 * si + x2 * co);
}

// ---------------- v prep: transpose to [b,h,d,S] f16 ------------------------
__global__ __launch_bounds__(256) void vprep(const float* __restrict__ qkv,
                                             __half* __restrict__ vtb)
{
    __shared__ float t[64][65];
    int s0 = blockIdx.x << 6, h = blockIdx.y, b = blockIdx.z;
    int tid = threadIdx.x;
#pragma unroll
    for (int p = 0; p < 16; ++p) {
        int r = (p << 2) + (tid >> 6), d = tid & 63;
        t[r][d] = qkv[((size_t)(b * SS + s0 + r) * 3 + 2) * DIMV + h * 64 + d];
    }
    __syncthreads();
    size_t ob = ((size_t)(b * NH + h) * 64) * SS;
#pragma unroll
    for (int p = 0; p < 16; ++p) {
        int d = (p << 2) + (tid >> 6), sl = tid & 63;
        vtb[ob + (size_t)d * SS + s0 + sl] = __float2half(t[sl][d]);
    }
}

// ---------------- flash attention, f16 HMMA ---------------------------------
__global__ void __launch_bounds__(128) attn_mma(
    const __half* __restrict__ qs, const __half* __restrict__ ks,
    const __half* __restrict__ vt, __nv_bfloat16* __restrict__ ctxb)
{
    __shared__ __align__(16) char sm[40960];   // Q 8KB | 2 x (K 8KB + V 8KB)
    const uint32_t Qs = smem_u32(sm);
    const uint32_t Ss = Qs + 8192;
    const int qt = gridDim.x - 1 - blockIdx.x;  // heavy tiles first
    const int h = blockIdx.y, b = blockIdx.z;
    const int q0 = qt << 6;
    const int tid = threadIdx.x, wid = tid >> 5, lane = tid & 31;
    const int quad = lane >> 3, l8 = lane & 7;
    const int tr = lane >> 2, tc = (lane & 3) << 1;
    const int wq0 = wid << 4;
    const size_t bh = (size_t)(b * NH + h);
    const __half* qrow = qs + (bh * SS + q0) * 64;
    const __half* krow = ks + bh * SS * 64;
    const __half* vrow = vt + bh * 64 * SS;

    for (int c = tid; c < 512; c += 128) {
        int r = c >> 3, kc = c & 7;
        cpa16(Qs + r * 128 + ((kc ^ (r & 7)) << 4),
              (const char*)(qrow + (size_t)r * 64) + kc * 16);
    }
    CP_COMMIT();

    auto load_stage = [&](int kt) {
        uint32_t Kst = Ss + (kt & 1) * 16384, Vst = Kst + 8192;
        const __half* kr = krow + ((size_t)kt << 6) * 64;
        int k0 = kt << 6;
        for (int c = tid; c < 512; c += 128) {
            int r = c >> 3, kc = c & 7;
            cpa16(Kst + r * 128 + ((kc ^ (r & 7)) << 4),
                  (const char*)(kr + (size_t)r * 64) + kc * 16);
        }
        for (int c = tid; c < 512; c += 128) {
            int r = c >> 3, kc = c & 7;
            cpa16(Vst + r * 128 + ((kc ^ (r & 7)) << 4),
                  (const char*)(vrow + (size_t)r * SS + k0) + kc * 16);
        }
        CP_COMMIT();
    };

    float m0r = -1e30f, m1r = -1e30f, l0 = 0.f, l1 = 0.f;
    float oacc[8][4];
#pragma unroll
    for (int i = 0; i < 8; ++i)
#pragma unroll
        for (int j = 0; j < 4; ++j) oacc[i][j] = 0.f;

    const int nt = qt + 1;
    load_stage(0);

    for (int kt = 0; kt < nt; ++kt) {
        if (kt + 1 < nt) {
            load_stage(kt + 1);
            asm volatile("cp.async.wait_group 1;" ::: "memory");
        } else {
            asm volatile("cp.async.wait_group 0;" ::: "memory");
        }
        __syncthreads();
        const uint32_t Kst = Ss + (kt & 1) * 16384, Vst = Kst + 8192;

        float sacc[8][4];
#pragma unroll
        for (int i = 0; i < 8; ++i)
#pragma unroll
            for (int j = 0; j < 4; ++j) sacc[i][j] = 0.f;
#pragma unroll
        for (int ksp = 0; ksp < 4; ++ksp) {
            uint32_t a[4];
            {
                int r = wq0 + ((quad & 1) << 3) + l8;
                int kc = 2 * ksp + (quad >> 1);
                LDSM4(a, Qs + r * 128 + ((kc ^ (r & 7)) << 4));
            }
#pragma unroll
            for (int np = 0; np < 4; ++np) {
                uint32_t bf[4];
                int r = (np << 4) + ((quad >> 1) << 3) + l8;
                int kc = 2 * ksp + (quad & 1);
                LDSM4(bf, Kst + r * 128 + ((kc ^ (r & 7)) << 4));
                MMAF16(sacc[2 * np],     a, bf[0], bf[1]);
                MMAF16(sacc[2 * np + 1], a, bf[2], bf[3]);
            }
        }

        if (kt == qt) {
            int r0 = wq0 + tr, r1 = r0 + 8;
#pragma unroll
            for (int nf = 0; nf < 8; ++nf) {
                int c0 = (nf << 3) + tc;
                if (c0     > r0) sacc[nf][0] = -1e30f;
                if (c0 + 1 > r0) sacc[nf][1] = -1e30f;
                if (c0     > r1) sacc[nf][2] = -1e30f;
                if (c0 + 1 > r1) sacc[nf][3] = -1e30f;
            }
        }

        float mx0 = -1e30f, mx1 = -1e30f;
#pragma unroll
        for (int nf = 0; nf < 8; ++nf) {
            mx0 = fmaxf(mx0, fmaxf(sacc[nf][0], sacc[nf][1]));
            mx1 = fmaxf(mx1, fmaxf(sacc[nf][2], sacc[nf][3]));
        }
        mx0 = fmaxf(mx0, __shfl_xor_sync(0xffffffffu, mx0, 1));
        mx0 = fmaxf(mx0, __shfl_xor_sync(0xffffffffu, mx0, 2));
        mx1 = fmaxf(mx1, __shfl_xor_sync(0xffffffffu, mx1, 1));
        mx1 = fmaxf(mx1, __shfl_xor_sync(0xffffffffu, mx1, 2));
        float mn0 = fmaxf(m0r, mx0), mn1 = fmaxf(m1r, mx1);
        float al0 = __expf(m0r - mn0), al1 = __expf(m1r - mn1);
        float rs0 = 0.f, rs1 = 0.f;
#pragma unroll
        for (int nf = 0; nf < 8; ++nf) {
            sacc[nf][0] = __expf(sacc[nf][0] - mn0);
            sacc[nf][1] = __expf(sacc[nf][1] - mn0);
            sacc[nf][2] = __expf(sacc[nf][2] - mn1);
            sacc[nf][3] = __expf(sacc[nf][3] - mn1);
            rs0 += sacc[nf][0] + sacc[nf][1];
            rs1 += sacc[nf][2] + sacc[nf][3];
        }
        rs0 += __shfl_xor_sync(0xffffffffu, rs0, 1);
        rs0 += __shfl_xor_sync(0xffffffffu, rs0, 2);
        rs1 += __shfl_xor_sync(0xffffffffu, rs1, 1);
        rs1 += __shfl_xor_sync(0xffffffffu, rs1, 2);
        l0 = l0 * al0 + rs0;
        l1 = l1 * al1 + rs1;
        m0r = mn0; m1r = mn1;
#pragma unroll
        for (int nf = 0; nf < 8; ++nf) {
            oacc[nf][0] *= al0; oacc[nf][1] *= al0;
            oacc[nf][2] *= al1; oacc[nf][3] *= al1;
        }

#pragma unroll
        for (int ksp = 0; ksp < 4; ++ksp) {
            uint32_t pa[4];
            pa[0] = pkf16(sacc[2 * ksp][0],     sacc[2 * ksp][1]);
            pa[1] = pkf16(sacc[2 * ksp][2],     sacc[2 * ksp][3]);
            pa[2] = pkf16(sacc[2 * ksp + 1][0], sacc[2 * ksp + 1][1]);
            pa[3] = pkf16(sacc[2 * ksp + 1][2], sacc[2 * ksp + 1][3]);
#pragma unroll
            for (int np = 0; np < 4; ++np) {
                uint32_t bf[4];
                int r = (np << 4) + ((quad >> 1) << 3) + l8;
                int kc = 2 * ksp + (quad & 1);
                LDSM4(bf, Vst + r * 128 + ((kc ^ (r & 7)) << 4));
                MMAF16(oacc[2 * np],     pa, bf[0], bf[1]);
                MMAF16(oacc[2 * np + 1], pa, bf[2], bf[3]);
            }
        }
        __syncthreads();
    }

    float i0 = 1.f / l0, i1 = 1.f / l1;
    int row0 = q0 + wq0 + tr;
    __nv_bfloat16* p0 = ctxb + ((size_t)b * SS + row0) * KP1 + h * 64;
    __nv_bfloat16* p1 = p0 + (size_t)8 * KP1;
#pragma unroll
    for (int nf = 0; nf < 8; ++nf) {
        int co = (nf << 3) + tc;
        float v0 = oacc[nf][0] * i0, v1 = oacc[nf][1] * i0;
        float v2 = oacc[nf][2] * i1, v3 = oacc[nf][3] * i1;
        __nv_bfloat16 h0 = __float2bfloat16(v0), h1 = __float2bfloat16(v1);
        __nv_bfloat16 h2 = __float2bfloat16(v2), h3 = __float2bfloat16(v3);
        __nv_bfloat162 hp0 = {h0, h1}, hp1 = {h2, h3};
        __nv_bfloat162 lp0 = {__float2bfloat16(v0 - __bfloat162float(h0)),
                              __float2bfloat16(v1 - __bfloat162float(h1))};
        __nv_bfloat162 lp1 = {__float2bfloat16(v2 - __bfloat162float(h2)),
                              __float2bfloat16(v3 - __bfloat162float(h3))};
        *(__nv_bfloat162*)(p0 + co)            = hp0;
        *(__nv_bfloat162*)(p0 + co + DIMV)     = hp0;
        *(__nv_bfloat162*)(p0 + co + 2 * DIMV) = lp0;
        *(__nv_bfloat162*)(p1 + co)            = hp1;
        *(__nv_bfloat162*)(p1 + co + DIMV)     = hp1;
        *(__nv_bfloat162*)(p1 + co + 2 * DIMV) = lp1;
    }
}

// ---------------- out = rms_norm(a + b) * scale  (+ optional bf16 split) ----
__global__ __launch_bounds__(256) void addnorm_kernel(
    const float* __restrict__ a, const float* __restrict__ bbuf,
    const float* __restrict__ scale, float* __restrict__ out,
    __nv_bfloat16* __restrict__ outb)
{
    const int row = blockIdx.x;
    const int tid = threadIdx.x;
    const size_t base = (size_t)row * DIMV;
    float v[4];
    float ss = 0.f;
#pragma unroll
    for (int j = 0; j < 4; ++j) {
        int c = tid + j * 256;
        v[j] = a[base + c] + bbuf[base + c];
        ss = fmaf(v[j], v[j], ss);
    }
    __shared__ float red[8];
#pragma unroll
    for (int o = 16; o; o >>= 1) ss += __shfl_xor_sync(0xffffffffu, ss, o);
    if ((tid & 31) == 0) red[tid >> 5] = ss;
    __syncthreads();
    if (tid < 8) {
        float t = red[tid];
#pragma unroll
        for (int o = 4; o; o >>= 1) t += __shfl_xor_sync(0xffu, t, o);
        if (tid == 0) red[0] = t;
    }
    __syncthreads();
    float rms = sqrtf(red[0] * (1.f / 1024.f));
    float inv = 1.f / (rms + 1e-8f);
#pragma unroll
    for (int j = 0; j < 4; ++j) {
        int c = tid + j * 256;
        float o = scale[c] * v[j] * inv;
        out[base + c] = o;
        if (outb) {
            __nv_bfloat16 hi = __float2bfloat16(o);
            __nv_bfloat16 lo = __float2bfloat16(o - __bfloat162float(hi));
            size_t bb2 = (size_t)row * KP1 + c;
            outb[bb2] = hi; outb[bb2 + DIMV] = hi; outb[bb2 + 2 * DIMV] = lo;
        }
    }
}

// ---------------- launcher --------------------------------------------------
extern "C" void kernel_launch(void* const* d_in, const int* in_sizes, int n_in,
                              void* d_out, int out_size)
{
    (void)in_sizes; (void)n_in; (void)out_size;
    const float* x          = (const float*)d_in[0];
    const float* qkv_w      = (const float*)d_in[2];
    const float* attn_out_w = (const float*)d_in[3];
    const float* gate_w     = (const float*)d_in[4];
    const float* gate_b     = (const float*)d_in[5];
    const float* lin_w      = (const float*)d_in[6];
    const float* lin_b      = (const float*)d_in[7];
    const float* ff_out_w   = (const float*)d_in[8];
    const float* n1         = (const float*)d_in[9];
    const float* n2         = (const float*)d_in[10];
    float* out = (float*)d_out;

    float *qkv, *tmp, *x1;
    __half *qsb, *ksb, *vtb;
    __nv_bfloat16 *xb, *ctxb, *x1b, *hb, *wqkv, *wao, *wgl, *wfo;
    cudaGetSymbolAddress((void**)&qkv,  g_qkv);
    cudaGetSymbolAddress((void**)&tmp,  g_tmp);
    cudaGetSymbolAddress((void**)&x1,   g_x1);
    cudaGetSymbolAddress((void**)&qsb,  g_qs);
    cudaGetSymbolAddress((void**)&ksb,  g_ks);
    cudaGetSymbolAddress((void**)&vtb,  g_vt);
    cudaGetSymbolAddress((void**)&xb,   g_xb);
    cudaGetSymbolAddress((void**)&ctxb, g_ctxb);
    cudaGetSymbolAddress((void**)&x1b,  g_x1b);
    cudaGetSymbolAddress((void**)&hb,   g_hb);
    cudaGetSymbolAddress((void**)&wqkv, g_wqkv);
    cudaGetSymbolAddress((void**)&wao,  g_wao);
    cudaGetSymbolAddress((void**)&wgl,  g_wgl);
    cudaGetSymbolAddress((void**)&wfo,  g_wfo);

    cudaFuncSetAttribute(gemm_mma_t<0>, cudaFuncAttributeMaxDynamicSharedMemorySize, GEMM_SMEM);
    cudaFuncSetAttribute(gemm_mma_t<1>, cudaFuncAttributeMaxDynamicSharedMemorySize, GEMM_SMEM);

    // weight + input conversions (fp32 -> split bf16)
    convert_w    <<<(3*DIMV*DIMV + 255)/256, 256>>>(qkv_w,      wqkv, 3*DIMV*DIMV, DIMV);
    convert_w    <<<(DIMV*DIMV   + 255)/256, 256>>>(attn_out_w, wao,  DIMV*DIMV,   DIMV);
    convert_w_glu<<<(FFV*DIMV    + 255)/256, 256>>>(gate_w, lin_w, wgl);
    convert_w    <<<(DIMV*FFV    + 255)/256, 256>>>(ff_out_w,   wfo,  DIMV*FFV,    FFV);
    convert_act  <<<(MTOT*DIMV   + 255)/256, 256>>>(x,          xb,   MTOT*DIMV,   DIMV);

    // 1. QKV projection
    gemm_mma_t<0><<<dim3(3*DIMV/128, MTOT/128), 256, GEMM_SMEM>>>(
        xb, wqkv, qkv, nullptr, nullptr, nullptr, 3*DIMV, KP1);
    // 2. q/k prep (RoPE + scale -> f16) and v transpose
    qkprep<<<(BB*SS*NH*32 + 255)/256, 256>>>(qkv, qsb, ksb);
    vprep <<<dim3(SS/64, NH, BB), 256>>>(qkv, vtb);
    // 3. flash attention (f16 HMMA) -> split-bf16 ctx
    attn_mma<<<dim3(SS/64, NH, BB), 128>>>(qsb, ksb, vtb, ctxb);
    // 4. output projection
    gemm_mma_t<0><<<dim3(DIMV/128, MTOT/128), 256, GEMM_SMEM>>>(
        ctxb, wao, tmp, nullptr, nullptr, nullptr, DIMV, KP1);
    // 5. x1 = rmsnorm(x + proj), also emit split bf16
    addnorm_kernel<<<MTOT, 256>>>(x, tmp, n1, x1, x1b);
    // 6-8. fused gate+lin GEMM with GLU epilogue -> split-bf16 hb
    gemm_mma_t<1><<<dim3(2*FFV/128, MTOT/128), 256, GEMM_SMEM>>>(
        x1b, wgl, nullptr, hb, gate_b, lin_b, 2*FFV, KP1);
    // 9. ff out
    gemm_mma_t<0><<<dim3(DIMV/128, MTOT/128), 256, GEMM_SMEM>>>(
        hb, wfo, tmp, nullptr, nullptr, nullptr, DIMV, KP2);
    // 10. out = rmsnorm(x1 + ff)
    addnorm_kernel<<<MTOT, 256>>>(x1, tmp, n2, out, nullptr);
}

// round 7
// speedup vs baseline: 1.5685x; 1.3956x over previous
#include <cuda_runtime.h>
#include <cuda_bf16.h>
#include <cuda_fp16.h>
#include <cstdint>
#include <math.h>

#define BB 2
#define SS 2048
#define DIMV 1024
#define NH 16
#define FFV 4096
#define MTOT (BB*SS)          /* 4096 rows */
#define KP1 (2*DIMV)          /* 2048: 2-term fp16 split for K=1024 */
#define KP2 (2*FFV)           /* 8192:  2-term fp16 split for K=4096 */

// ---------------- scratch (device globals: allocation-free) ----------------
__device__ float g_qkv[MTOT * 3 * DIMV];
__device__ float g_tmp[MTOT * DIMV];
__device__ float g_x1 [MTOT * DIMV];

__device__ __align__(16) __half g_qs[(size_t)BB * NH * SS * 64];
__device__ __align__(16) __half g_ks[(size_t)BB * NH * SS * 64];
__device__ __align__(16) __half g_vt[(size_t)BB * NH * 64 * SS];

__device__ __align__(16) __half g_xb  [MTOT * KP1];
__device__ __align__(16) __half g_ctxb[MTOT * KP1];
__device__ __align__(16) __half g_x1b [MTOT * KP1];
__device__ __align__(16) __half g_hb  [(size_t)MTOT * KP2];
__device__ __align__(16) __half g_wqkv[3 * DIMV * KP1];
__device__ __align__(16) __half g_wao [DIMV * KP1];
__device__ __align__(16) __half g_wgl [(size_t)2 * FFV * KP1];  // interleaved gate/lin
__device__ __align__(16) __half g_wfo [DIMV * KP2];

// ---------------- PTX helpers ----------------------------------------------
__device__ __forceinline__ uint32_t smem_u32(const void* p) {
    uint32_t a;
    asm("{ .reg .u64 t; cvta.to.shared.u64 t, %1; cvt.u32.u64 %0, t; }"
        : "=r"(a) : "l"(p));
    return a;
}
__device__ __forceinline__ void cpa16(uint32_t dst, const void* src) {
    asm volatile("cp.async.cg.shared.global [%0], [%1], 16;" :: "r"(dst), "l"(src));
}
#define CP_COMMIT() asm volatile("cp.async.commit_group;" ::: "memory")

#define LDSM4(r, addr) \
    asm volatile("ldmatrix.sync.aligned.m8n8.x4.shared.b16 {%0,%1,%2,%3}, [%4];" \
        : "=r"((r)[0]), "=r"((r)[1]), "=r"((r)[2]), "=r"((r)[3]) : "r"(addr))

#define MMAF16(d, a, b0, b1) \
    asm volatile("mma.sync.aligned.m16n8k16.row.col.f32.f16.f16.f32 " \
        "{%0,%1,%2,%3},{%4,%5,%6,%7},{%8,%9},{%0,%1,%2,%3};" \
        : "+f"((d)[0]), "+f"((d)[1]), "+f"((d)[2]), "+f"((d)[3]) \
        : "r"((a)[0]), "r"((a)[1]), "r"((a)[2]), "r"((a)[3]), "r"(b0), "r"(b1))

__device__ __forceinline__ uint32_t pkf16(float lo, float hi) {
    uint32_t r;
    asm("cvt.rn.f16x2.f32 %0, %1, %2;" : "=r"(r) : "f"(hi), "f"(lo));
    return r;
}

// ---------------- fp16 HMMA GEMM: C[M,N] = A[M,Kp] @ W[N,Kp]^T --------------
// CTA 128x128, 8 warps (2x4), warp 64x32, BK=64, 3-stage cp.async pipeline
// (96KB smem -> 2 CTAs/SM).
// EPI=0: plain fp32 store.  EPI=1: GLU epilogue (interleaved gate/lin cols)
//        h = (lin+lb)*sigmoid(gate+gb) -> 2-term fp16 HB [hi|lo] over KP2.
#define GSTAGES 3
#define GSTAGE_BYTES 32768          /* A 16KB + B 16KB */
#define GEMM_SMEM (GSTAGES * GSTAGE_BYTES)

template<int EPI>
__global__ void __launch_bounds__(256) gemm_mma_t(
    const __half* __restrict__ A, const __half* __restrict__ W,
    float* __restrict__ C, __half* __restrict__ HB,
    const float* __restrict__ gb, const float* __restrict__ lb,
    int N, int Kp)
{
    extern __shared__ char sm[];
    const uint32_t smb = smem_u32(sm);
    const int tid  = threadIdx.x;
    const int wid  = tid >> 5, lane = tid & 31;
    const int wm   = (wid >> 2) << 6;
    const int wn   = (wid & 3) << 5;
    const int m0   = blockIdx.y << 7, n0 = blockIdx.x << 7;
    const int quad = lane >> 3, l8 = lane & 7;

    float acc[4][4][4];
#pragma unroll
    for (int i = 0; i < 4; ++i)
#pragma unroll
        for (int j = 0; j < 4; ++j)
#pragma unroll
            for (int v = 0; v < 4; ++v) acc[i][j][v] = 0.f;

    auto load_stage = [&](int kt) {
        const int s = kt % GSTAGES;
        const uint32_t sa = smb + s * GSTAGE_BYTES;
        const uint32_t sb = sa + 16384;
        const size_t kbase = (size_t)kt << 6;
#pragma unroll
        for (int p = 0; p < 4; ++p) {
            int chunk = (p << 8) + tid;
            int r = chunk >> 3, kc = chunk & 7;
            cpa16(sa + r * 128 + ((kc ^ (r & 7)) << 4),
                  (const char*)(A + (size_t)(m0 + r) * Kp + kbase + kc * 8));
        }
#pragma unroll
        for (int p = 0; p < 4; ++p) {
            int chunk = (p << 8) + tid;
            int r = chunk >> 3, kc = chunk & 7;
            cpa16(sb + r * 128 + ((kc ^ (r & 7)) << 4),
                  (const char*)(W + (size_t)(n0 + r) * Kp + kbase + kc * 8));
        }
        CP_COMMIT();
    };

    const int nk = Kp >> 6;
    load_stage(0);
    load_stage(1);

    for (int kt = 0; kt < nk; ++kt) {
        const int s = kt % GSTAGES;
        asm volatile("cp.async.wait_group 1;" ::: "memory");
        __syncthreads();
        if (kt + 2 < nk) load_stage(kt + 2); else CP_COMMIT();

        const uint32_t sa = smb + s * GSTAGE_BYTES;
        const uint32_t sb = sa + 16384;
#pragma unroll
        for (int ks = 0; ks < 4; ++ks) {
            const int k0c = ks << 1;
            uint32_t a[4][4], b[2][4];
#pragma unroll
            for (int mf = 0; mf < 4; ++mf) {
                int r  = wm + (mf << 4) + ((quad & 1) << 3) + l8;
                int kc = k0c + (quad >> 1);
                LDSM4(a[mf], sa + r * 128 + ((kc ^ (r & 7)) << 4));
            }
#pragma unroll
            for (int np = 0; np < 2; ++np) {
                int r  = wn + (np << 4) + ((quad >> 1) << 3) + l8;
                int kc = k0c + (quad & 1);
                LDSM4(b[np], sb + r * 128 + ((kc ^ (r & 7)) << 4));
            }
#pragma unroll
            for (int mf = 0; mf < 4; ++mf) {
#pragma unroll
                for (int np = 0; np < 2; ++np) {
                    MMAF16(acc[mf][2 * np],     a[mf], b[np][0], b[np][1]);
                    MMAF16(acc[mf][2 * np + 1], a[mf], b[np][2], b[np][3]);
                }
            }
        }
    }

    const int tr = lane >> 2, tc = (lane & 3) << 1;
    if (EPI == 0) {
#pragma unroll
        for (int mf = 0; mf < 4; ++mf) {
            int row = m0 + wm + (mf << 4) + tr;
            float* c0 = C + (size_t)row * N + n0 + wn;
            float* c1 = c0 + (size_t)8 * N;
#pragma unroll
            for (int nf = 0; nf < 4; ++nf) {
                *(float2*)(c0 + (nf << 3) + tc) = make_float2(acc[mf][nf][0], acc[mf][nf][1]);
                *(float2*)(c1 + (nf << 3) + tc) = make_float2(acc[mf][nf][2], acc[mf][nf][3]);
            }
        }
    } else {
        // interleaved cols: even col = gate_c, odd col = lin_c, c = gcol>>1.
        // lane pairs (lane, lane^1) hold consecutive c -> even lanes store f16x2.
#pragma unroll
        for (int mf = 0; mf < 4; ++mf) {
            int row0 = m0 + wm + (mf << 4) + tr;
#pragma unroll
            for (int nf = 0; nf < 4; ++nf) {
                int c = (n0 + wn + (nf << 3) + tc) >> 1;
                float gbv = gb[c], lbv = lb[c];
                float h0 = (acc[mf][nf][1] + lbv) *
                           (1.f / (1.f + __expf(-(acc[mf][nf][0] + gbv))));
                float h1 = (acc[mf][nf][3] + lbv) *
                           (1.f / (1.f + __expf(-(acc[mf][nf][2] + gbv))));
                float h0p = __shfl_xor_sync(0xffffffffu, h0, 1);
                float h1p = __shfl_xor_sync(0xffffffffu, h1, 1);
                if ((lane & 1) == 0) {
                    __half a0 = __float2half_rn(h0),  b0 = __float2half_rn(h0p);
                    __half a1 = __float2half_rn(h1),  b1 = __float2half_rn(h1p);
                    __half2 hi0 = {a0, b0}, hi1 = {a1, b1};
                    __half2 lo0 = {__float2half_rn(h0  - __half2float(a0)),
                                   __float2half_rn(h0p - __half2float(b0))};
                    __half2 lo1 = {__float2half_rn(h1  - __half2float(a1)),
                                   __float2half_rn(h1p - __half2float(b1))};
                    __half* p0 = HB + (size_t)row0 * KP2 + c;
                    __half* p1 = p0 + (size_t)8 * KP2;
                    *(__half2*)(p0)       = hi0;
                    *(__half2*)(p0 + FFV) = lo0;
                    *(__half2*)(p1)       = hi1;
                    *(__half2*)(p1 + FFV) = lo1;
                }
            }
        }
    }
}

// ---------------- fp32 -> fp16 conversions ----------------------------------
// activations: [hi | lo] along K'; weights: [hi | hi] (duplicated)
__global__ void convert_act(const float* __restrict__ X, __half* __restrict__ Y,
                            int total, int K)
{
    int idx = blockIdx.x * blockDim.x + threadIdx.x;
    if (idx >= total) return;
    int row = idx / K, col = idx - row * K;
    float x = X[idx];
    __half hi = __float2half_rn(x);
    __half lo = __float2half_rn(x - __half2float(hi));
    size_t b = (size_t)row * (2 * K) + col;
    Y[b] = hi; Y[b + K] = lo;
}
__global__ void convert_w(const float* __restrict__ X, __half* __restrict__ Y,
                          int total, int K)
{
    int idx = blockIdx.x * blockDim.x + threadIdx.x;
    if (idx >= total) return;
    int row = idx / K, col = idx - row * K;
    __half hi = __float2half_rn(X[idx]);
    size_t b = (size_t)row * (2 * K) + col;
    Y[b] = hi; Y[b + K] = hi;
}
// gate row c -> interleaved row 2c ; lin row c -> row 2c+1  ([hi|hi])
__global__ void convert_w_glu(const float* __restrict__ G, const float* __restrict__ L,
                              __half* __restrict__ Y)
{
    int idx = blockIdx.x * blockDim.x + threadIdx.x;
    if (idx >= FFV * DIMV) return;
    int row = idx >> 10, col = idx & (DIMV - 1);
    __half gh = __float2half_rn(G[idx]);
    __half lh = __float2half_rn(L[idx]);
    size_t bg = (size_t)(2 * row) * KP1 + col;
    size_t bl = bg + KP1;
    Y[bg] = gh; Y[bg + DIMV] = gh;
    Y[bl] = lh; Y[bl + DIMV] = lh;
}

// ---------------- q,k prep: RoPE + scale + f16, head-major layout -----------
__global__ void qkprep(const float* __restrict__ qkv,
                       __half* __restrict__ qs, __half* __restrict__ ks)
{
    int idx = blockIdx.x * blockDim.x + threadIdx.x;
    if (idx >= BB * SS * NH * 32) return;
    int i = idx & 31;
    int h = (idx >> 5) & 15;
    int s = (idx >> 9) & (SS - 1);
    int b = idx >> 20;
    float inv_freq = expf(-(float)i * (9.210340371976184f / 32.0f));
    float ph = (float)s * inv_freq;
    float co = cosf(ph), si = sinf(ph);
    size_t base = ((size_t)(b * SS + s) * 3) * DIMV + h * 64;
    size_t ob = ((size_t)(b * NH + h) * SS + s) * 64;
    float x1 = qkv[base + i], x2 = qkv[base + 32 + i];
    qs[ob + i]      = __float2half((x1 * co - x2 * si) * 0.125f);
    qs[ob + 32 + i] = __float2half((x1 * si + x2 * co) * 0.125f);
    base += DIMV;
    x1 = qkv[base + i]; x2 = qkv[base + 32 + i];
    ks[ob + i]      = __float2half(x1 * co - x2 * si);
    ks[ob + 32 + i] = __float2half(x1 * si + x2 * co);
}

// ---------------- v prep: transpose to [b,h,d,S] f16 ------------------------
__global__ __launch_bounds__(256) void vprep(const float* __restrict__ qkv,
                                             __half* __restrict__ vtb)
{
    __shared__ float t[64][65];
    int s0 = blockIdx.x << 6, h = blockIdx.y, b = blockIdx.z;
    int tid = threadIdx.x;
#pragma unroll
    for (int p = 0; p < 16; ++p) {
        int r = (p << 2) + (tid >> 6), d = tid & 63;
        t[r][d] = qkv[((size_t)(b * SS + s0 + r) * 3 + 2) * DIMV + h * 64 + d];
    }
    __syncthreads();
    size_t ob = ((size_t)(b * NH + h) * 64) * SS;
#pragma unroll
    for (int p = 0; p < 16; ++p) {
        int d = (p << 2) + (tid >> 6), sl = tid & 63;
        vtb[ob + (size_t)d * SS + s0 + sl] = __float2half(t[sl][d]);
    }
}

// ---------------- flash attention, f16 HMMA ---------------------------------
// Epilogue writes ctx directly as 2-term fp16 [hi|lo] for the out-proj GEMM.
__global__ void __launch_bounds__(128) attn_mma(
    const __half* __restrict__ qs, const __half* __restrict__ ks,
    const __half* __restrict__ vt, __half* __restrict__ ctxb)
{
    __shared__ __align__(16) char sm[40960];   // Q 8KB | 2 x (K 8KB + V 8KB)
    const uint32_t Qs = smem_u32(sm);
    const uint32_t Ss = Qs + 8192;
    const int qt = gridDim.x - 1 - blockIdx.x;  // heavy tiles first
    const int h = blockIdx.y, b = blockIdx.z;
    const int q0 = qt << 6;
    const int tid = threadIdx.x, wid = tid >> 5, lane = tid & 31;
    const int quad = lane >> 3, l8 = lane & 7;
    const int tr = lane >> 2, tc = (lane & 3) << 1;
    const int wq0 = wid << 4;
    const size_t bh = (size_t)(b * NH + h);
    const __half* qrow = qs + (bh * SS + q0) * 64;
    const __half* krow = ks + bh * SS * 64;
    const __half* vrow = vt + bh * 64 * SS;

    for (int c = tid; c < 512; c += 128) {
        int r = c >> 3, kc = c & 7;
        cpa16(Qs + r * 128 + ((kc ^ (r & 7)) << 4),
              (const char*)(qrow + (size_t)r * 64) + kc * 16);
    }
    CP_COMMIT();

    auto load_stage = [&](int kt) {
        uint32_t Kst = Ss + (kt & 1) * 16384, Vst = Kst + 8192;
        const __half* kr = krow + ((size_t)kt << 6) * 64;
        int k0 = kt << 6;
        for (int c = tid; c < 512; c += 128) {
            int r = c >> 3, kc = c & 7;
            cpa16(Kst + r * 128 + ((kc ^ (r & 7)) << 4),
                  (const char*)(kr + (size_t)r * 64) + kc * 16);
        }
        for (int c = tid; c < 512; c += 128) {
            int r = c >> 3, kc = c & 7;
            cpa16(Vst + r * 128 + ((kc ^ (r & 7)) << 4),
                  (const char*)(vrow + (size_t)r * SS + k0) + kc * 16);
        }
        CP_COMMIT();
    };

    float m0r = -1e30f, m1r = -1e30f, l0 = 0.f, l1 = 0.f;
    float oacc[8][4];
#pragma unroll
    for (int i = 0; i < 8; ++i)
#pragma unroll
        for (int j = 0; j < 4; ++j) oacc[i][j] = 0.f;

    const int nt = qt + 1;
    load_stage(0);

    for (int kt = 0; kt < nt; ++kt) {
        if (kt + 1 < nt) {
            load_stage(kt + 1);
            asm volatile("cp.async.wait_group 1;" ::: "memory");
        } else {
            asm volatile("cp.async.wait_group 0;" ::: "memory");
        }
        __syncthreads();
        const uint32_t Kst = Ss + (kt & 1) * 16384, Vst = Kst + 8192;

        float sacc[8][4];
#pragma unroll
        for (int i = 0; i < 8; ++i)
#pragma unroll
            for (int j = 0; j < 4; ++j) sacc[i][j] = 0.f;
#pragma unroll
        for (int ksp = 0; ksp < 4; ++ksp) {
            uint32_t a[4];
            {
                int r = wq0 + ((quad & 1) << 3) + l8;
                int kc = 2 * ksp + (quad >> 1);
                LDSM4(a, Qs + r * 128 + ((kc ^ (r & 7)) << 4));
            }
#pragma unroll
            for (int np = 0; np < 4; ++np) {
                uint32_t bf[4];
                int r = (np << 4) + ((quad >> 1) << 3) + l8;
                int kc = 2 * ksp + (quad & 1);
                LDSM4(bf, Kst + r * 128 + ((kc ^ (r & 7)) << 4));
                MMAF16(sacc[2 * np],     a, bf[0], bf[1]);
                MMAF16(sacc[2 * np + 1], a, bf[2], bf[3]);
            }
        }

        if (kt == qt) {
            int r0 = wq0 + tr, r1 = r0 + 8;
#pragma unroll
            for (int nf = 0; nf < 8; ++nf) {
                int c0 = (nf << 3) + tc;
                if (c0     > r0) sacc[nf][0] = -1e30f;
                if (c0 + 1 > r0) sacc[nf][1] = -1e30f;
                if (c0     > r1) sacc[nf][2] = -1e30f;
                if (c0 + 1 > r1) sacc[nf][3] = -1e30f;
            }
        }

        float mx0 = -1e30f, mx1 = -1e30f;
#pragma unroll
        for (int nf = 0; nf < 8; ++nf) {
            mx0 = fmaxf(mx0, fmaxf(sacc[nf][0], sacc[nf][1]));
            mx1 = fmaxf(mx1, fmaxf(sacc[nf][2], sacc[nf][3]));
        }
        mx0 = fmaxf(mx0, __shfl_xor_sync(0xffffffffu, mx0, 1));
        mx0 = fmaxf(mx0, __shfl_xor_sync(0xffffffffu, mx0, 2));
        mx1 = fmaxf(mx1, __shfl_xor_sync(0xffffffffu, mx1, 1));
        mx1 = fmaxf(mx1, __shfl_xor_sync(0xffffffffu, mx1, 2));
        float mn0 = fmaxf(m0r, mx0), mn1 = fmaxf(m1r, mx1);
        float al0 = __expf(m0r - mn0), al1 = __expf(m1r - mn1);
        float rs0 = 0.f, rs1 = 0.f;
#pragma unroll
        for (int nf = 0; nf < 8; ++nf) {
            sacc[nf][0] = __expf(sacc[nf][0] - mn0);
            sacc[nf][1] = __expf(sacc[nf][1] - mn0);
            sacc[nf][2] = __expf(sacc[nf][2] - mn1);
            sacc[nf][3] = __expf(sacc[nf][3] - mn1);
            rs0 += sacc[nf][0] + sacc[nf][1];
            rs1 += sacc[nf][2] + sacc[nf][3];
        }
        rs0 += __shfl_xor_sync(0xffffffffu, rs0, 1);
        rs0 += __shfl_xor_sync(0xffffffffu, rs0, 2);
        rs1 += __shfl_xor_sync(0xffffffffu, rs1, 1);
        rs1 += __shfl_xor_sync(0xffffffffu, rs1, 2);
        l0 = l0 * al0 + rs0;
        l1 = l1 * al1 + rs1;
        m0r = mn0; m1r = mn1;
#pragma unroll
        for (int nf = 0; nf < 8; ++nf) {
            oacc[nf][0] *= al0; oacc[nf][1] *= al0;
            oacc[nf][2] *= al1; oacc[nf][3] *= al1;
        }

#pragma unroll
        for (int ksp = 0; ksp < 4; ++ksp) {
            uint32_t pa[4];
            pa[0] = pkf16(sacc[2 * ksp][0],     sacc[2 * ksp][1]);
            pa[1] = pkf16(sacc[2 * ksp][2],     sacc[2 * ksp][3]);
            pa[2] = pkf16(sacc[2 * ksp + 1][0], sacc[2 * ksp + 1][1]);
            pa[3] = pkf16(sacc[2 * ksp + 1][2], sacc[2 * ksp + 1][3]);
#pragma unroll
            for (int np = 0; np < 4; ++np) {
                uint32_t bf[4];
                int r = (np << 4) + ((quad >> 1) << 3) + l8;
                int kc = 2 * ksp + (quad & 1);
                LDSM4(bf, Vst + r * 128 + ((kc ^ (r & 7)) << 4));
                MMAF16(oacc[2 * np],     pa, bf[0], bf[1]);
                MMAF16(oacc[2 * np + 1], pa, bf[2], bf[3]);
            }
        }
        __syncthreads();
    }

    float i0 = 1.f / l0, i1 = 1.f / l1;
    int row0 = q0 + wq0 + tr;
    __half* p0 = ctxb + ((size_t)b * SS + row0) * KP1 + h * 64;
    __half* p1 = p0 + (size_t)8 * KP1;
#pragma unroll
    for (int nf = 0; nf < 8; ++nf) {
        int co = (nf << 3) + tc;
        float v0 = oacc[nf][0] * i0, v1 = oacc[nf][1] * i0;
        float v2 = oacc[nf][2] * i1, v3 = oacc[nf][3] * i1;
        __half h0 = __float2half_rn(v0), h1 = __float2half_rn(v1);
        __half h2 = __float2half_rn(v2), h3 = __float2half_rn(v3);
        __half2 hp0 = {h0, h1}, hp1 = {h2, h3};
        __half2 lp0 = {__float2half_rn(v0 - __half2float(h0)),
                       __float2half_rn(v1 - __half2float(h1))};
        __half2 lp1 = {__float2half_rn(v2 - __half2float(h2)),
                       __float2half_rn(v3 - __half2float(h3))};
        *(__half2*)(p0 + co)        = hp0;
        *(__half2*)(p0 + co + DIMV) = lp0;
        *(__half2*)(p1 + co)        = hp1;
        *(__half2*)(p1 + co + DIMV) = lp1;
    }
}

// ---------------- out = rms_norm(a + b) * scale  (+ optional fp16 split) ----
__global__ __launch_bounds__(256) void addnorm_kernel(
    const float* __restrict__ a, const float* __restrict__ bbuf,
    const float* __restrict__ scale, float* __restrict__ out,
    __half* __restrict__ outb)
{
    const int row = blockIdx.x;
    const int tid = threadIdx.x;
    const size_t base = (size_t)row * DIMV;
    float v[4];
    float ss = 0.f;
#pragma unroll
    for (int j = 0; j < 4; ++j) {
        int c = tid + j * 256;
        v[j] = a[base + c] + bbuf[base + c];
        ss = fmaf(v[j], v[j], ss);
    }
    __shared__ float red[8];
#pragma unroll
    for (int o = 16; o; o >>= 1) ss += __shfl_xor_sync(0xffffffffu, ss, o);
    if ((tid & 31) == 0) red[tid >> 5] = ss;
    __syncthreads();
    if (tid < 8) {
        float t = red[tid];
#pragma unroll
        for (int o = 4; o; o >>= 1) t += __shfl_xor_sync(0xffu, t, o);
        if (tid == 0) red[0] = t;
    }
    __syncthreads();
    float rms = sqrtf(red[0] * (1.f / 1024.f));
    float inv = 1.f / (rms + 1e-8f);
#pragma unroll
    for (int j = 0; j < 4; ++j) {
        int c = tid + j * 256;
        float o = scale[c] * v[j] * inv;
        out[base + c] = o;
        if (outb) {
            __half hi = __float2half_rn(o);
            __half lo = __float2half_rn(o - __half2float(hi));
            size_t bb2 = (size_t)row * KP1 + c;
            outb[bb2] = hi; outb[bb2 + DIMV] = lo;
        }
    }
}

// ---------------- launcher --------------------------------------------------
extern "C" void kernel_launch(void* const* d_in, const int* in_sizes, int n_in,
                              void* d_out, int out_size)
{
    (void)in_sizes; (void)n_in; (void)out_size;
    const float* x          = (const float*)d_in[0];
    const float* qkv_w      = (const float*)d_in[2];
    const float* attn_out_w = (const float*)d_in[3];
    const float* gate_w     = (const float*)d_in[4];
    const float* gate_b     = (const float*)d_in[5];
    const float* lin_w      = (const float*)d_in[6];
    const float* lin_b      = (const float*)d_in[7];
    const float* ff_out_w   = (const float*)d_in[8];
    const float* n1         = (const float*)d_in[9];
    const float* n2         = (const float*)d_in[10];
    float* out = (float*)d_out;

    float *qkv, *tmp, *x1;
    __half *qsb, *ksb, *vtb;
    __half *xb, *ctxb, *x1b, *hb, *wqkv, *wao, *wgl, *wfo;
    cudaGetSymbolAddress((void**)&qkv,  g_qkv);
    cudaGetSymbolAddress((void**)&tmp,  g_tmp);
    cudaGetSymbolAddress((void**)&x1,   g_x1);
    cudaGetSymbolAddress((void**)&qsb,  g_qs);
    cudaGetSymbolAddress((void**)&ksb,  g_ks);
    cudaGetSymbolAddress((void**)&vtb,  g_vt);
    cudaGetSymbolAddress((void**)&xb,   g_xb);
    cudaGetSymbolAddress((void**)&ctxb, g_ctxb);
    cudaGetSymbolAddress((void**)&x1b,  g_x1b);
    cudaGetSymbolAddress((void**)&hb,   g_hb);
    cudaGetSymbolAddress((void**)&wqkv, g_wqkv);
    cudaGetSymbolAddress((void**)&wao,  g_wao);
    cudaGetSymbolAddress((void**)&wgl,  g_wgl);
    cudaGetSymbolAddress((void**)&wfo,  g_wfo);

    cudaFuncSetAttribute(gemm_mma_t<0>, cudaFuncAttributeMaxDynamicSharedMemorySize, GEMM_SMEM);
    cudaFuncSetAttribute(gemm_mma_t<1>, cudaFuncAttributeMaxDynamicSharedMemorySize, GEMM_SMEM);

    // weight + input conversions (fp32 -> fp16 2-term layout)
    convert_w    <<<(3*DIMV*DIMV + 255)/256, 256>>>(qkv_w,      wqkv, 3*DIMV*DIMV, DIMV);
    convert_w    <<<(DIMV*DIMV   + 255)/256, 256>>>(attn_out_w, wao,  DIMV*DIMV,   DIMV);
    convert_w_glu<<<(FFV*DIMV    + 255)/256, 256>>>(gate_w, lin_w, wgl);
    convert_w    <<<(DIMV*FFV    + 255)/256, 256>>>(ff_out_w,   wfo,  DIMV*FFV,    FFV);
    convert_act  <<<(MTOT*DIMV   + 255)/256, 256>>>(x,          xb,   MTOT*DIMV,   DIMV);

    // 1. QKV projection
    gemm_mma_t<0><<<dim3(3*DIMV/128, MTOT/128), 256, GEMM_SMEM>>>(
        xb, wqkv, qkv, nullptr, nullptr, nullptr, 3*DIMV, KP1);
    // 2. q/k prep (RoPE + scale -> f16) and v transpose
    qkprep<<<(BB*SS*NH*32 + 255)/256, 256>>>(qkv, qsb, ksb);
    vprep <<<dim3(SS/64, NH, BB), 256>>>(qkv, vtb);
    // 3. flash attention (f16 HMMA) -> 2-term fp16 ctx
    attn_mma<<<dim3(SS/64, NH, BB), 128>>>(qsb, ksb, vtb, ctxb);
    // 4. output projection
    gemm_mma_t<0><<<dim3(DIMV/128, MTOT/128), 256, GEMM_SMEM>>>(
        ctxb, wao, tmp, nullptr, nullptr, nullptr, DIMV, KP1);
    // 5. x1 = rmsnorm(x + proj), also emit 2-term fp16
    addnorm_kernel<<<MTOT, 256>>>(x, tmp, n1, x1, x1b);
    // 6-8. fused gate+lin GEMM with GLU epilogue -> 2-term fp16 hb
    gemm_mma_t<1><<<dim3(2*FFV/128, MTOT/128), 256, GEMM_SMEM>>>(
        x1b, wgl, nullptr, hb, gate_b, lin_b, 2*FFV, KP1);
    // 9. ff out
    gemm_mma_t<0><<<dim3(DIMV/128, MTOT/128), 256, GEMM_SMEM>>>(
        hb, wfo, tmp, nullptr, nullptr, nullptr, DIMV, KP2);
    // 10. out = rmsnorm(x1 + ff)
    addnorm_kernel<<<MTOT, 256>>>(x1, tmp, n2, out, nullptr);
}